// round 9
// baseline (speedup 1.0000x reference)
#include <cuda_runtime.h>
#include <cuda_bf16.h>

// Fixed problem shape
#define BB 8
#define NN 4096
#define EE 64
#define KK 32

#define DELTA_V 0.5f
#define DELTA_D 1.5f
#define GAMMA   0.001f

#define G1 256            // K1/K3 blocks
#define TPB 512
#define PTS 128           // points per K1/K3 block
#define SMEM_DYN (PTS * EE * 4)   // 32KB x stash in k_partial

// Scratch ------------------------------------------------------------------
__device__ float    g_part[G1 * KK * EE];   // per-block centroid partial sums (2MB)
__device__ float    g_pcnt[G1 * KK];        // per-block cluster counts
__device__ float    g_cent[BB * KK * EE];   // normalized centroids
__device__ int      g_lab[BB * NN];         // labels
__device__ float    g_acc[3];               // L_v, L_d, L_r (unnormalized)
__device__ unsigned g_bar = 0;              // K3 finalize counter (reset each run)

// ===========================================================================
// K1: overlapped x-stash + labels, counting sort, per-bin sums from SMEM
// ===========================================================================
__global__ void __launch_bounds__(TPB) k_partial(const float* __restrict__ x,
                                                 const float* __restrict__ m) {
    extern __shared__ float sx[];             // [PTS*EE] x stash
    __shared__ int slab[PTS];
    __shared__ int ssorted[PTS];
    __shared__ int sbin[KK], soff[KK], scur[KK];

    int tid = threadIdx.x, lane = tid & 31, warp = tid >> 5;
    int blk = blockIdx.x;
    int pbase = blk * PTS;

    if (tid < KK) sbin[tid] = 0;
    if (blk == 0 && tid < 3) g_acc[tid] = 0.0f;

    // ---- issue ALL x loads first (4 independent float4 per thread) --------
    const float4* x4 = (const float4*)(x + (size_t)pbase * EE);
    float4 r0 = x4[tid];
    float4 r1 = x4[tid + TPB];
    float4 r2 = x4[tid + 2 * TPB];
    float4 r3 = x4[tid + 3 * TPB];

    // ---- mask loads + labels overlap with x loads in flight ----------------
    #pragma unroll
    for (int it = 0; it < 2; ++it) {
        int p  = it * 64 + warp * 4 + (lane >> 3);
        int k0 = (lane & 7) * 4;
        float4 mv = *(const float4*)(m + (size_t)(pbase + p) * KK + k0);
        float s = mv.x * k0 + mv.y * (k0 + 1) + mv.z * (k0 + 2) + mv.w * (k0 + 3);
        s += __shfl_xor_sync(0xffffffffu, s, 1);
        s += __shfl_xor_sync(0xffffffffu, s, 2);
        s += __shfl_xor_sync(0xffffffffu, s, 4);
        if ((lane & 7) == 0) slab[p] = (int)(s + 0.5f);
    }

    // ---- land x in SMEM ----------------------------------------------------
    float4* sx4 = (float4*)sx;
    sx4[tid]           = r0;
    sx4[tid + TPB]     = r1;
    sx4[tid + 2 * TPB] = r2;
    sx4[tid + 3 * TPB] = r3;
    __syncthreads();

    // ---- counting sort -----------------------------------------------------
    if (tid < PTS) atomicAdd(&sbin[slab[tid]], 1);
    __syncthreads();
    if (tid < KK) {
        int c = sbin[tid];
        int pref = c;
        #pragma unroll
        for (int o = 1; o < 32; o <<= 1) {
            int nv = __shfl_up_sync(0xffffffffu, pref, o);
            if (lane >= o) pref += nv;
        }
        soff[tid] = pref - c;
        scur[tid] = pref - c;
    }
    __syncthreads();
    if (tid < PTS) {
        int pos = atomicAdd(&scur[slab[tid]], 1);
        ssorted[pos] = tid;
        g_lab[pbase + tid] = slab[tid];       // persist labels for K3
    }
    __syncthreads();

    // ---- per-bin accumulation from SMEM (no atomics, no DRAM latency) ------
    #pragma unroll
    for (int kb = 0; kb < 2; ++kb) {
        int k = warp * 2 + kb;
        int start = soff[k], cnt = sbin[k], end = start + cnt;
        float ax = 0.0f, ay = 0.0f;
        for (int base = start; base < end; base += 4) {
            float2 v0 = {0,0}, v1 = {0,0}, v2 = {0,0}, v3 = {0,0};
            v0 = *(const float2*)(sx + ssorted[base] * EE + lane * 2);
            if (base + 1 < end) v1 = *(const float2*)(sx + ssorted[base+1] * EE + lane * 2);
            if (base + 2 < end) v2 = *(const float2*)(sx + ssorted[base+2] * EE + lane * 2);
            if (base + 3 < end) v3 = *(const float2*)(sx + ssorted[base+3] * EE + lane * 2);
            ax += (v0.x + v1.x) + (v2.x + v3.x);
            ay += (v0.y + v1.y) + (v2.y + v3.y);
        }
        float2 acc = {ax, ay};
        *(float2*)(&g_part[(size_t)blk * (KK*EE) + k * EE + lane * 2]) = acc;
        if (lane == 0) g_pcnt[blk * KK + k] = (float)cnt;
    }
}

// ===========================================================================
// K2: block i reduces (b,k)-row i -> normalized g_cent. 256 blocks x 256 thr.
// ===========================================================================
__global__ void __launch_bounds__(256) k_reduce() {
    __shared__ float part[256];
    __shared__ float s_cntinv;
    int tid = threadIdx.x, lane = tid & 31;
    int rb = blockIdx.x >> 5, rk = blockIdx.x & 31;

    if (tid < 32) {                     // sum 32 partial counts
        float c = __ldcg(&g_pcnt[((rb << 5) | lane) * KK + rk]);
        #pragma unroll
        for (int o = 16; o; o >>= 1) c += __shfl_xor_sync(0xffffffffu, c, o);
        if (lane == 0) s_cntinv = 1.0f / c;
    }

    int e = tid & 63, q = tid >> 6;     // 4 groups of 64, 8 slices each
    float s = 0.0f;
    #pragma unroll
    for (int j = 0; j < 8; ++j)
        s += __ldcg(&g_part[(size_t)((rb << 5) | (q * 8 + j)) * (KK*EE) + rk * EE + e]);
    part[q * 64 + e] = s;
    __syncthreads();
    if (tid < EE) {
        float t = ((part[tid] + part[64 + tid]) + (part[128 + tid] + part[192 + tid]));
        g_cent[rb * (KK*EE) + rk * EE + tid] = t * s_cntinv;
    }
}

// ===========================================================================
// K3: variance hinge (all blocks) + pairs/reg (8 blocks) + finalize
// ===========================================================================
__global__ void __launch_bounds__(TPB) k_loss(const float* __restrict__ x,
                                              float* __restrict__ out) {
    __shared__ float sc[KK * EE];
    __shared__ float ct[KK * EE];
    __shared__ int   slab[PTS];
    __shared__ float bsum;

    int tid = threadIdx.x, lane = tid & 31;
    int blk = blockIdx.x;
    int pbase = blk * PTS;
    int b = blk >> 5;

    if (tid == 0) bsum = 0.0f;
    ((float4*)sc)[tid] = __ldcg(((const float4*)(g_cent + b * (KK*EE))) + tid);
    if (tid < PTS) slab[tid] = g_lab[pbase + tid];
    __syncthreads();

    // variance hinge: 16-lane group per point, 2-pt ILP, x from warm L2
    {
        int gid = tid >> 4, gl = tid & 15;
        float lv = 0.0f;
        #pragma unroll
        for (int it = 0; it < 2; ++it) {
            int iA = it * 64 + gid;
            int iB = iA + 32;
            int labA = slab[iA], labB = slab[iB];
            float4 xA = *(const float4*)(x + (size_t)(pbase + iA) * EE + gl * 4);
            float4 xB = *(const float4*)(x + (size_t)(pbase + iB) * EE + gl * 4);
            float4 cA = ((const float4*)sc)[labA * 16 + gl];
            float4 cB = ((const float4*)sc)[labB * 16 + gl];
            float a0 = xA.x - cA.x, a1 = xA.y - cA.y, a2 = xA.z - cA.z, a3 = xA.w - cA.w;
            float b0 = xB.x - cB.x, b1 = xB.y - cB.y, b2 = xB.z - cB.z, b3 = xB.w - cB.w;
            float sqA = a0 * a0 + a1 * a1 + a2 * a2 + a3 * a3;
            float sqB = b0 * b0 + b1 * b1 + b2 * b2 + b3 * b3;
            #pragma unroll
            for (int o = 8; o; o >>= 1) {
                sqA += __shfl_xor_sync(0xffffffffu, sqA, o);
                sqB += __shfl_xor_sync(0xffffffffu, sqB, o);
            }
            if (gl == 0) {
                float hA = sqrtf(sqA) - DELTA_V;
                float hB = sqrtf(sqB) - DELTA_V;
                if (hA > 0.0f) lv += hA * hA;
                if (hB > 0.0f) lv += hB * hB;
            }
        }
        if (gl == 0) atomicAdd(&bsum, lv);
        __syncthreads();
        if (tid == 0) atomicAdd(&g_acc[0], bsum);
    }

    // pairwise hinge + reg term (one block per batch)
    if ((blk & 31) == 0) {
        for (int i = tid; i < KK * EE; i += TPB) {
            int e = i >> 5, k = i & 31;
            ct[i] = sc[k * EE + e];            // transposed, lane-contiguous
        }
        __syncthreads();

        float ld = 0.0f, lr = 0.0f;
        #pragma unroll
        for (int rep = 0; rep < 2; ++rep) {
            int pr = rep * TPB + tid;
            int k1 = pr >> 5, k2 = pr & 31;
            float sq = 0.0f;
            if (k1 == k2) {
                #pragma unroll
                for (int e = 0; e < EE; e++) { float v = sc[k1 * EE + e]; sq += v * v; }
                lr += sqrtf(sq);
            } else {
                #pragma unroll
                for (int e = 0; e < EE; e++) {
                    float d = sc[k1 * EE + e] - ct[e * KK + k2];
                    sq += d * d;
                }
                float h = 2.0f * DELTA_D - sqrtf(sq);
                if (h > 0.0f) ld += h * h;
            }
        }
        #pragma unroll
        for (int o = 16; o; o >>= 1) {
            ld += __shfl_xor_sync(0xffffffffu, ld, o);
            lr += __shfl_xor_sync(0xffffffffu, lr, o);
        }
        if (lane == 0) {
            atomicAdd(&g_acc[1], ld);
            atomicAdd(&g_acc[2], lr);
        }
    }

    // finalize: last arrival writes output (no spinning)
    __syncthreads();
    if (tid == 0) {
        __threadfence();
        unsigned r = atomicAdd(&g_bar, 1u);
        if (r == G1 - 1) {
            float Lv = *(volatile float*)&g_acc[0] / (float)(BB * NN);
            float Ld = *(volatile float*)&g_acc[1] / (float)(BB * KK * (KK - 1));
            float Lr = *(volatile float*)&g_acc[2] / (float)(BB * KK);
            out[0] = Lv + Ld + GAMMA * Lr;
            __threadfence();
            atomicExch(&g_bar, 0u);            // ready for next replay
        }
    }
}

// --------------------------------------------------------------------------
extern "C" void kernel_launch(void* const* d_in, const int* in_sizes, int n_in,
                              void* d_out, int out_size) {
    const float* x = (const float*)d_in[0];
    const float* m = (const float*)d_in[1];
    if (in_sizes[0] == BB * NN * KK && in_sizes[1] == BB * NN * EE) {
        x = (const float*)d_in[1];
        m = (const float*)d_in[0];
    }
    cudaFuncSetAttribute(k_partial, cudaFuncAttributeMaxDynamicSharedMemorySize, SMEM_DYN);
    k_partial<<<G1, TPB, SMEM_DYN>>>(x, m);
    k_reduce<<<G1, 256>>>();
    k_loss<<<G1, TPB>>>(x, (float*)d_out);
}